// round 3
// baseline (speedup 1.0000x reference)
#include <cuda_runtime.h>

#define BB 4
#define MM 2048
#define HH 16
#define CHUNKS 16
#define NWARP 8

// partial attention outputs: one plane per chunk -> summed in ln kernel (no atomics, deterministic)
__device__ float g_part[CHUNKS][BB * MM];
__device__ float g_G2[256];   // [sm*16+sn] = SCALE*log2(e) * dot(wq_seg(sm), wk_seg(sn))
__device__ float g_Gvf[256];  // [sn*16+s ] = dot(wv_seg(sn), w_final_seg(s))

__device__ __forceinline__ float ex2f(float x) {
    float r; asm("ex2.approx.ftz.f32 %0, %1;" : "=f"(r) : "f"(x)); return r;
}
__device__ __forceinline__ float rcpf(float x) {
    float r; asm("rcp.approx.ftz.f32 %0, %1;" : "=f"(r) : "f"(x)); return r;
}

__global__ void prep_kernel(const float* __restrict__ wq, const float* __restrict__ wk,
                            const float* __restrict__ wv, const float* __restrict__ wf) {
    int t = threadIdx.x;           // 256 threads
    int i = t >> 4, j = t & 15;
    if (blockIdx.x == 0) {
        const float* a = wq + i * 128;
        const float* b = wk + j * 128;
        float s = 0.f;
        #pragma unroll 8
        for (int d = 0; d < 128; d++) s = fmaf(a[d], b[d], s);
        // fold softmax scale (8^-0.5) and log2(e) into the score matrix
        g_G2[t] = s * (0.35355339059327373f * 1.4426950408889634f);
    } else {
        const float* a = wv + i * 128;
        const float* b = wf + j * 128;
        float s = 0.f;
        #pragma unroll 8
        for (int d = 0; d < 128; d++) s = fmaf(a[d], b[d], s);
        g_Gvf[t] = s;   // indexed [sn][s]
    }
}

__global__ __launch_bounds__(256)
void attn_kernel(const float* __restrict__ query, const float* __restrict__ key,
                 const float* __restrict__ value) {
    __shared__ float s_q[128], s_k[128], s_v[128];
    __shared__ float s_G2[256], s_Gvf[256];
    __shared__ float s_wacc[NWARP][128];

    int bh    = blockIdx.x / CHUNKS;   // 0..63  (= b*16 + h)
    int chunk = blockIdx.x % CHUNKS;   // 0..15
    int base  = bh * 128;              // == b*2048 + h*128
    int t = threadIdx.x;

    if (t < 128) {
        s_q[t] = query[base + t];
        s_k[t] = key[base + t];
        s_v[t] = value[base + t];
    }
    s_G2[t]  = g_G2[t];
    s_Gvf[t] = g_Gvf[t];
    __syncthreads();

    int warp = t >> 5, lane = t & 31;
    int rn = chunk * NWARP + warp;     // each warp owns one rn in [0,128)
    float kvr = s_k[rn];
    float vvr = s_v[rn];
    float p0 = s_q[lane]      * kvr;
    float p1 = s_q[lane + 32] * kvr;
    float p2 = s_q[lane + 64] * kvr;
    float p3 = s_q[lane + 96] * kvr;

    float a0 = 0.f, a1 = 0.f, a2 = 0.f, a3 = 0.f;

    for (int sn = 0; sn < 16; sn++) {
        float z0 = 0.f, z1 = 0.f, z2 = 0.f, z3 = 0.f;
        float d0 = 0.f, d1 = 0.f, d2 = 0.f, d3 = 0.f;
        #pragma unroll
        for (int s = 0; s < 16; s++) {
            float g  = s_G2[s * 16 + sn];
            float gv = s_Gvf[sn * 16 + s];
            float w0 = ex2f(p0 * g);
            float w1 = ex2f(p1 * g);
            float w2 = ex2f(p2 * g);
            float w3 = ex2f(p3 * g);
            z0 += w0; z1 += w1; z2 += w2; z3 += w3;
            d0 = fmaf(w0, gv, d0);
            d1 = fmaf(w1, gv, d1);
            d2 = fmaf(w2, gv, d2);
            d3 = fmaf(w3, gv, d3);
        }
        float z = (z0 + z1) + (z2 + z3);
        #pragma unroll
        for (int o = 16; o; o >>= 1) z += __shfl_xor_sync(0xffffffffu, z, o);
        float sc = vvr * rcpf(z);     // vv[rn] / Z[rn,sn]
        a0 = fmaf(d0, sc, a0);
        a1 = fmaf(d1, sc, a1);
        a2 = fmaf(d2, sc, a2);
        a3 = fmaf(d3, sc, a3);
    }

    s_wacc[warp][lane]      = a0;
    s_wacc[warp][lane + 32] = a1;
    s_wacc[warp][lane + 64] = a2;
    s_wacc[warp][lane + 96] = a3;
    __syncthreads();

    if (t < 128) {
        float s = 0.f;
        #pragma unroll
        for (int w = 0; w < NWARP; w++) s += s_wacc[w][t];
        g_part[chunk][base + t] = s;
    }
}

__device__ __forceinline__ float block_reduce_512(float v, float* sred) {
    #pragma unroll
    for (int o = 16; o; o >>= 1) v += __shfl_xor_sync(0xffffffffu, v, o);
    int warp = threadIdx.x >> 5, lane = threadIdx.x & 31;
    if (lane == 0) sred[warp] = v;
    __syncthreads();
    if (threadIdx.x == 0) {
        float s = sred[0];
        #pragma unroll
        for (int w = 1; w < 16; w++) s += sred[w];
        sred[0] = s;
    }
    __syncthreads();
    float r = sred[0];
    __syncthreads();   // protect sred for the next call
    return r;
}

__global__ __launch_bounds__(512)
void ln_kernel(const float* __restrict__ query, const float* __restrict__ lnw,
               const float* __restrict__ lnb, float* __restrict__ out) {
    __shared__ float sx[2048];
    __shared__ float sred[16];
    int b = blockIdx.x, t = threadIdx.x;   // 512 threads

    float loc = 0.f;
    for (int i = t; i < 2048; i += 512) {
        float x = query[b * 2048 + i];     // residual
        #pragma unroll
        for (int c = 0; c < CHUNKS; c++) x += g_part[c][b * 2048 + i];
        sx[i] = x;
        loc += x;
    }
    float mu = block_reduce_512(loc, sred) * (1.f / 2048.f);

    float lv = 0.f;
    for (int i = t; i < 2048; i += 512) {
        float d = sx[i] - mu;
        lv = fmaf(d, d, lv);
    }
    float var = block_reduce_512(lv, sred) * (1.f / 2048.f);
    float rstd = rsqrtf(var + 1e-5f);

    for (int i = t; i < 2048; i += 512) {
        out[b * 2048 + i] = (sx[i] - mu) * rstd * lnw[i] + lnb[i];
    }
}

extern "C" void kernel_launch(void* const* d_in, const int* in_sizes, int n_in,
                              void* d_out, int out_size) {
    const float* query = (const float*)d_in[0];
    const float* key   = (const float*)d_in[1];
    const float* value = (const float*)d_in[2];
    const float* wq    = (const float*)d_in[3];
    const float* wk    = (const float*)d_in[4];
    const float* wv    = (const float*)d_in[5];
    const float* wf    = (const float*)d_in[6];
    const float* lnw   = (const float*)d_in[7];
    const float* lnb   = (const float*)d_in[8];
    float* out = (float*)d_out;

    prep_kernel<<<2, 256>>>(wq, wk, wv, wf);
    attn_kernel<<<BB * HH * CHUNKS, 256>>>(query, key, value);
    ln_kernel<<<BB, 512>>>(query, lnw, lnb, out);
}

// round 4
// speedup vs baseline: 4.0170x; 4.0170x over previous
#include <cuda_runtime.h>

#define NTERM 17           // Taylor terms n = 0..16
#define SCALE 0.35355339059327373f

// weight-only precompute:  [n*16+sn]
__device__ float g_Gn[NTERM * 16];   // (sum_sm g^n) / n!
__device__ float g_Hn[NTERM * 16];   // (sum_sm g^n * Gvf[sn][sm]) / n!
__device__ float g_attn[4 * 2048];   // attention output (pre-residual)

__constant__ float c_invfact[NTERM] = {
    1.0f, 1.0f, 0.5f, 1.0f/6.0f, 1.0f/24.0f, 1.0f/120.0f, 1.0f/720.0f,
    1.0f/5040.0f, 1.0f/40320.0f, 1.0f/362880.0f, 1.0f/3628800.0f,
    1.0f/39916800.0f, 1.0f/479001600.0f, 1.0f/6227020800.0f,
    1.0f/87178291200.0f, 1.0f/1307674368000.0f, 1.0f/20922789888000.0f
};

__device__ __forceinline__ float rcpf(float x) {
    float r; asm("rcp.approx.ftz.f32 %0, %1;" : "=f"(r) : "f"(x)); return r;
}

// ───────────────────────── prep: g, Gvf → Gn, Hn ─────────────────────────
__global__ __launch_bounds__(256)
void prep_kernel(const float* __restrict__ wq, const float* __restrict__ wk,
                 const float* __restrict__ wv, const float* __restrict__ wf) {
    __shared__ float s_wq[2048], s_wv[2048];
    __shared__ float s_wk[16 * 129], s_wf[16 * 129];   // pitch 129 → conflict-free
    __shared__ float s_g[16][16];    // [sm][sn] = SCALE * dot(wq_seg sm, wk_seg sn)
    __shared__ float s_gvf[16][16];  // [sn][sm] = dot(wv_seg sn, wf_seg sm)
    int t = threadIdx.x;

    for (int i = t; i < 2048; i += 256) { s_wq[i] = wq[i]; s_wv[i] = wv[i]; }
    for (int i = t; i < 2048; i += 256) {
        int r = i >> 7, d = i & 127;
        s_wk[r * 129 + d] = wk[i];
        s_wf[r * 129 + d] = wf[i];
    }
    __syncthreads();

    int i = t >> 4, j = t & 15;
    {
        const float* a = s_wq + i * 128;   // broadcast across 16 threads
        const float* b = s_wk + j * 129;   // conflict-free
        float s = 0.f;
        #pragma unroll 16
        for (int d = 0; d < 128; d++) s = fmaf(a[d], b[d], s);
        s_g[i][j] = s * SCALE;
    }
    {
        const float* a = s_wv + i * 128;
        const float* b = s_wf + j * 129;
        float s = 0.f;
        #pragma unroll 16
        for (int d = 0; d < 128; d++) s = fmaf(a[d], b[d], s);
        s_gvf[i][j] = s;                   // [sn=i][sm=j]
    }
    __syncthreads();

    if (t < 16) {
        int sn = t;
        float G[NTERM], H[NTERM];
        #pragma unroll
        for (int n = 0; n < NTERM; n++) { G[n] = 0.f; H[n] = 0.f; }
        #pragma unroll
        for (int sm = 0; sm < 16; sm++) {
            float x = s_g[sm][sn];
            float gv = s_gvf[sn][sm];
            float p = 1.f;
            #pragma unroll
            for (int n = 0; n < NTERM; n++) {
                G[n] += p;
                H[n] = fmaf(p, gv, H[n]);
                p *= x;
            }
        }
        #pragma unroll
        for (int n = 0; n < NTERM; n++) {
            g_Gn[n * 16 + sn] = G[n] * c_invfact[n];
            g_Hn[n * 16 + sn] = H[n] * c_invfact[n];
        }
    }
}

// ───────────────────────── attention via Taylor separation ─────────────────────────
__global__ __launch_bounds__(128)
void attn_kernel(const float* __restrict__ query, const float* __restrict__ key,
                 const float* __restrict__ value) {
    __shared__ float s_c[NTERM][16];     // Qn * Gn'[sn]
    __shared__ float s_H[NTERM][16];
    __shared__ float s_red[4][NTERM];
    __shared__ float s_Q[NTERM];
    __shared__ float s_C[NTERM];

    int base = blockIdx.x * 128;         // bh * 128 == b*2048 + h*128
    int t = threadIdx.x;
    int warp = t >> 5, lane = t & 31;

    float qv = query[base + t];
    float kv = key[base + t];
    float vv = value[base + t];

    // Qn = sum_rm qv^n  (block reduction of 17 powers)
    float v[NTERM];
    v[0] = 1.f;
    #pragma unroll
    for (int n = 1; n < NTERM; n++) v[n] = v[n - 1] * qv;
    #pragma unroll
    for (int o = 16; o; o >>= 1) {
        #pragma unroll
        for (int n = 0; n < NTERM; n++) v[n] += __shfl_xor_sync(0xffffffffu, v[n], o);
    }
    if (lane == 0) {
        #pragma unroll
        for (int n = 0; n < NTERM; n++) s_red[warp][n] = v[n];
    }
    __syncthreads();
    if (t < NTERM) s_Q[t] = s_red[0][t] + s_red[1][t] + s_red[2][t] + s_red[3][t];
    __syncthreads();

    // coefficient tables
    for (int idx = t; idx < NTERM * 16; idx += 128) {
        int n = idx >> 4, sn = idx & 15;
        s_c[n][sn] = s_Q[n] * g_Gn[idx];
        s_H[n][sn] = g_Hn[idx];
    }
    __syncthreads();

    // Z[rn,sn] via Horner in kv; W = 1/Z
    float W[16];
    #pragma unroll
    for (int sn = 0; sn < 16; sn++) {
        float z = s_c[NTERM - 1][sn];
        #pragma unroll
        for (int n = NTERM - 2; n >= 0; n--) z = fmaf(z, kv, s_c[n][sn]);
        W[sn] = rcpf(z);
    }

    // T[n] = sum_sn Hn'[sn] * W[sn];   then u_n = kv^n * vv * T[n]
    float T[NTERM];
    #pragma unroll
    for (int n = 0; n < NTERM; n++) {
        float s = 0.f;
        #pragma unroll
        for (int sn = 0; sn < 16; sn++) s = fmaf(s_H[n][sn], W[sn], s);
        T[n] = s;
    }
    float kp = vv;
    #pragma unroll
    for (int n = 0; n < NTERM; n++) { T[n] *= kp; kp *= kv; }

    // C[n] = block-sum of u_n
    #pragma unroll
    for (int o = 16; o; o >>= 1) {
        #pragma unroll
        for (int n = 0; n < NTERM; n++) T[n] += __shfl_xor_sync(0xffffffffu, T[n], o);
    }
    if (lane == 0) {
        #pragma unroll
        for (int n = 0; n < NTERM; n++) s_red[warp][n] = T[n];
    }
    __syncthreads();
    if (t < NTERM) s_C[t] = s_red[0][t] + s_red[1][t] + s_red[2][t] + s_red[3][t];
    __syncthreads();

    // out[rm] = sum_n qv^n * C[n]  (Horner)
    float r = s_C[NTERM - 1];
    #pragma unroll
    for (int n = NTERM - 2; n >= 0; n--) r = fmaf(r, qv, s_C[n]);
    g_attn[base + t] = r;
}

// ───────────────────────── residual + LayerNorm (single pass) ─────────────────────────
__global__ __launch_bounds__(512)
void ln_kernel(const float* __restrict__ query, const float* __restrict__ lnw,
               const float* __restrict__ lnb, float* __restrict__ out) {
    __shared__ float s_red[2][16];
    int b = blockIdx.x, t = threadIdx.x;
    int warp = t >> 5, lane = t & 31;

    const float4* q4 = (const float4*)(query + b * 2048);
    const float4* a4 = (const float4*)(g_attn + b * 2048);
    float4 x = q4[t];
    float4 a = a4[t];
    x.x += a.x; x.y += a.y; x.z += a.z; x.w += a.w;

    float s  = (x.x + x.y) + (x.z + x.w);
    float s2 = fmaf(x.x, x.x, fmaf(x.y, x.y, fmaf(x.z, x.z, x.w * x.w)));
    #pragma unroll
    for (int o = 16; o; o >>= 1) {
        s  += __shfl_xor_sync(0xffffffffu, s,  o);
        s2 += __shfl_xor_sync(0xffffffffu, s2, o);
    }
    if (lane == 0) { s_red[0][warp] = s; s_red[1][warp] = s2; }
    __syncthreads();
    float ts = 0.f, ts2 = 0.f;
    #pragma unroll
    for (int w = 0; w < 16; w++) { ts += s_red[0][w]; ts2 += s_red[1][w]; }

    float mu  = ts * (1.f / 2048.f);
    float var = ts2 * (1.f / 2048.f) - mu * mu;
    float rstd = rsqrtf(var + 1e-5f);

    const float4* w4 = (const float4*)lnw;
    const float4* b4 = (const float4*)lnb;
    float4 w = w4[t], bb = b4[t];
    float4 o;
    o.x = (x.x - mu) * rstd * w.x + bb.x;
    o.y = (x.y - mu) * rstd * w.y + bb.y;
    o.z = (x.z - mu) * rstd * w.z + bb.z;
    o.w = (x.w - mu) * rstd * w.w + bb.w;
    ((float4*)(out + b * 2048))[t] = o;
}

extern "C" void kernel_launch(void* const* d_in, const int* in_sizes, int n_in,
                              void* d_out, int out_size) {
    const float* query = (const float*)d_in[0];
    const float* key   = (const float*)d_in[1];
    const float* value = (const float*)d_in[2];
    const float* wq    = (const float*)d_in[3];
    const float* wk    = (const float*)d_in[4];
    const float* wv    = (const float*)d_in[5];
    const float* wf    = (const float*)d_in[6];
    const float* lnw   = (const float*)d_in[7];
    const float* lnb   = (const float*)d_in[8];
    float* out = (float*)d_out;

    prep_kernel<<<1, 256>>>(wq, wk, wv, wf);
    attn_kernel<<<64, 128>>>(query, key, value);
    ln_kernel<<<4, 512>>>(query, lnw, lnb, out);
}

// round 5
// speedup vs baseline: 5.0500x; 1.2571x over previous
#include <cuda_runtime.h>

#define NT 13              // Taylor terms n = 0..12
#define SCALE 0.35355339059327373f

__device__ float g_attn[4 * 2048];   // attention output (pre-residual)

__constant__ float c_invfact[NT] = {
    1.0f, 1.0f, 0.5f, 1.0f/6.0f, 1.0f/24.0f, 1.0f/120.0f, 1.0f/720.0f,
    1.0f/5040.0f, 1.0f/40320.0f, 1.0f/362880.0f, 1.0f/3628800.0f,
    1.0f/39916800.0f, 1.0f/479001600.0f
};

__device__ __forceinline__ float rcpf(float x) {
    float r; asm("rcp.approx.ftz.f32 %0, %1;" : "=f"(r) : "f"(x)); return r;
}

// ── fused: weight tables + Taylor-separated attention ──
// grid = 16 blocks × 512 threads; block handles 512 consecutive elements
// (= 4 heads of one batch row). One weight-dot per thread.
__global__ __launch_bounds__(512)
void fused_attn(const float* __restrict__ q, const float* __restrict__ k,
                const float* __restrict__ v,
                const float* __restrict__ wq, const float* __restrict__ wk,
                const float* __restrict__ wv, const float* __restrict__ wf) {
    __shared__ float s_wq[2048], s_wv[2048];        // linear (broadcast operand)
    __shared__ float s_wk[16 * 132], s_wf[16 * 132]; // pitch 132 → near conflict-free
    __shared__ float s_g[16][17];    // [sm][sn] = SCALE * dot(wq_seg sm, wk_seg sn)
    __shared__ float s_gv[16][17];   // [sn][sm] = dot(wv_seg sn, wf_seg sm)
    __shared__ float s_G[NT][16];    // (sum_sm g^n)/n!
    __shared__ float s_Hn[NT][16];   // (sum_sm g^n * gvf)/n!
    __shared__ float s_red[16][NT];  // per-warp reduction slots
    __shared__ float s_Q[4][NT];     // per-head sum of qv^n
    __shared__ float s_c[4 * NT * 16];
    __shared__ float s_C[4][NT + 3];

    int t = threadIdx.x;
    int lane = t & 31, warp = t >> 5;
    int base = blockIdx.x * 512;

    float qv = q[base + t];
    float kv = k[base + t];
    float vv = v[base + t];

    // stage weights (1 float4 per thread per array)
    ((float4*)s_wq)[t] = ((const float4*)wq)[t];
    ((float4*)s_wv)[t] = ((const float4*)wv)[t];
    {
        int rr = t >> 5, dd = (t & 31) << 2;
        *(float4*)(s_wk + rr * 132 + dd) = ((const float4*)wk)[t];
        *(float4*)(s_wf + rr * 132 + dd) = ((const float4*)wf)[t];
    }
    __syncthreads();

    // 512 dot-products, one per thread
    {
        int u = t & 255, i = u >> 4, j = u & 15;
        const float* A = (t < 256) ? (s_wq + i * 128) : (s_wv + i * 128);
        const float* B = (t < 256) ? (s_wk + j * 132) : (s_wf + j * 132);
        float s0 = 0.f, s1 = 0.f, s2 = 0.f, s3 = 0.f;
        #pragma unroll
        for (int d = 0; d < 128; d += 4) {
            s0 = fmaf(A[d + 0], B[d + 0], s0);
            s1 = fmaf(A[d + 1], B[d + 1], s1);
            s2 = fmaf(A[d + 2], B[d + 2], s2);
            s3 = fmaf(A[d + 3], B[d + 3], s3);
        }
        float s = (s0 + s1) + (s2 + s3);
        if (t < 256) s_g[i][j] = s * SCALE;   // [sm][sn]
        else         s_gv[i][j] = s;          // [sn][sm]
    }
    __syncthreads();

    // Gn/Hn tables: thread (sn,sm) for t<256; reduce over sm = low 4 lane bits
    if (t < 256) {
        int sn = t >> 4, sm = t & 15;
        float x  = s_g[sm][sn];
        float gv = s_gv[sn][sm];
        float p = 1.f;
        #pragma unroll
        for (int n = 0; n < NT; n++) {
            float Gs = p, Hs = p * gv;
            #pragma unroll
            for (int o = 1; o < 16; o <<= 1) {
                Gs += __shfl_xor_sync(0xffffffffu, Gs, o);
                Hs += __shfl_xor_sync(0xffffffffu, Hs, o);
            }
            if (sm == 0) {
                s_G[n][sn]  = Gs * c_invfact[n];
                s_Hn[n][sn] = Hs * c_invfact[n];
            }
            p *= x;
        }
    }

    // Qn per head: powers of qv, warp-reduce, cross-warp via smem
    {
        float pw[NT];
        pw[0] = 1.f;
        #pragma unroll
        for (int n = 1; n < NT; n++) pw[n] = pw[n - 1] * qv;
        #pragma unroll
        for (int o = 16; o; o >>= 1) {
            #pragma unroll
            for (int n = 0; n < NT; n++) pw[n] += __shfl_xor_sync(0xffffffffu, pw[n], o);
        }
        if (lane == 0) {
            #pragma unroll
            for (int n = 0; n < NT; n++) s_red[warp][n] = pw[n];
        }
    }
    __syncthreads();

    if (t < 4 * NT) {
        int h = t / NT, n = t - h * NT;
        s_Q[h][n] = (s_red[4 * h][n] + s_red[4 * h + 1][n])
                  + (s_red[4 * h + 2][n] + s_red[4 * h + 3][n]);
    }
    __syncthreads();

    // per-head Horner coefficients c[h][n][sn] = Q[h][n] * Gn[n][sn]
    for (int idx = t; idx < 4 * NT * 16; idx += 512) {
        int h = idx / (NT * 16);
        int rem = idx - h * (NT * 16);
        int n = rem >> 4, sn = rem & 15;
        s_c[idx] = s_Q[h][n] * s_G[n][sn];
    }
    __syncthreads();

    // core: Z[rn,sn] Horner in kv → W = 1/Z; T[n] = sum_sn Hn[sn]*W[sn]
    int h = t >> 7;
    const float* ch = s_c + h * (NT * 16);
    float W[16];
    #pragma unroll
    for (int sn = 0; sn < 16; sn++) {
        float z = ch[(NT - 1) * 16 + sn];
        #pragma unroll
        for (int n = NT - 2; n >= 0; n--) z = fmaf(z, kv, ch[n * 16 + sn]);
        W[sn] = rcpf(z);
    }
    float T[NT];
    #pragma unroll
    for (int n = 0; n < NT; n++) {
        float s = 0.f;
        #pragma unroll
        for (int sn = 0; sn < 16; sn++) s = fmaf(s_Hn[n][sn], W[sn], s);
        T[n] = s;
    }
    float kp = vv;
    #pragma unroll
    for (int n = 0; n < NT; n++) { T[n] *= kp; kp *= kv; }

    // C[n] per head = reduce T over the head's 128 lanes
    #pragma unroll
    for (int o = 16; o; o >>= 1) {
        #pragma unroll
        for (int n = 0; n < NT; n++) T[n] += __shfl_xor_sync(0xffffffffu, T[n], o);
    }
    if (lane == 0) {
        #pragma unroll
        for (int n = 0; n < NT; n++) s_red[warp][n] = T[n];
    }
    __syncthreads();
    if (t < 4 * NT) {
        int hh = t / NT, n = t - hh * NT;
        s_C[hh][n] = (s_red[4 * hh][n] + s_red[4 * hh + 1][n])
                   + (s_red[4 * hh + 2][n] + s_red[4 * hh + 3][n]);
    }
    __syncthreads();

    // out[rm] = sum_n qv^n * C[n]   (Horner)
    float r = s_C[h][NT - 1];
    #pragma unroll
    for (int n = NT - 2; n >= 0; n--) r = fmaf(r, qv, s_C[h][n]);
    g_attn[base + t] = r;
}

// ── residual + LayerNorm, single pass ──
__global__ __launch_bounds__(512)
void ln_kernel(const float* __restrict__ query, const float* __restrict__ lnw,
               const float* __restrict__ lnb, float* __restrict__ out) {
    __shared__ float s_red[2][16];
    int b = blockIdx.x, t = threadIdx.x;
    int warp = t >> 5, lane = t & 31;

    const float4* q4 = (const float4*)(query + b * 2048);
    const float4* a4 = (const float4*)(g_attn + b * 2048);
    float4 x = q4[t];
    float4 a = a4[t];
    x.x += a.x; x.y += a.y; x.z += a.z; x.w += a.w;

    float s  = (x.x + x.y) + (x.z + x.w);
    float s2 = fmaf(x.x, x.x, fmaf(x.y, x.y, fmaf(x.z, x.z, x.w * x.w)));
    #pragma unroll
    for (int o = 16; o; o >>= 1) {
        s  += __shfl_xor_sync(0xffffffffu, s,  o);
        s2 += __shfl_xor_sync(0xffffffffu, s2, o);
    }
    if (lane == 0) { s_red[0][warp] = s; s_red[1][warp] = s2; }
    __syncthreads();
    float ts = 0.f, ts2 = 0.f;
    #pragma unroll
    for (int w = 0; w < 16; w++) { ts += s_red[0][w]; ts2 += s_red[1][w]; }

    float mu   = ts * (1.f / 2048.f);
    float var  = ts2 * (1.f / 2048.f) - mu * mu;
    float rstd = rsqrtf(var + 1e-5f);

    float4 w = ((const float4*)lnw)[t];
    float4 bb = ((const float4*)lnb)[t];
    float4 o;
    o.x = (x.x - mu) * rstd * w.x + bb.x;
    o.y = (x.y - mu) * rstd * w.y + bb.y;
    o.z = (x.z - mu) * rstd * w.z + bb.z;
    o.w = (x.w - mu) * rstd * w.w + bb.w;
    ((float4*)(out + b * 2048))[t] = o;
}

extern "C" void kernel_launch(void* const* d_in, const int* in_sizes, int n_in,
                              void* d_out, int out_size) {
    const float* query = (const float*)d_in[0];
    const float* key   = (const float*)d_in[1];
    const float* value = (const float*)d_in[2];
    const float* wq    = (const float*)d_in[3];
    const float* wk    = (const float*)d_in[4];
    const float* wv    = (const float*)d_in[5];
    const float* wf    = (const float*)d_in[6];
    const float* lnw   = (const float*)d_in[7];
    const float* lnb   = (const float*)d_in[8];
    float* out = (float*)d_out;

    fused_attn<<<16, 512>>>(query, key, value, wq, wk, wv, wf);
    ln_kernel<<<4, 512>>>(query, lnw, lnb, out);
}

// round 6
// speedup vs baseline: 5.3025x; 1.0500x over previous
#include <cuda_runtime.h>

#define NT 11              // Taylor terms n = 0..10
#define SCALE 0.35355339059327373f

// cross-block LN reduction slots (per batch row), replay-safe reset protocol
__device__ float    g_sums[4][4][2];
__device__ unsigned g_arrive[4];
__device__ unsigned g_done[4];

__constant__ float c_invfact[NT] = {
    1.0f, 1.0f, 0.5f, 1.0f/6.0f, 1.0f/24.0f, 1.0f/120.0f, 1.0f/720.0f,
    1.0f/5040.0f, 1.0f/40320.0f, 1.0f/362880.0f, 1.0f/3628800.0f
};

__device__ __forceinline__ float rcpf(float x) {
    float r; asm("rcp.approx.ftz.f32 %0, %1;" : "=f"(r) : "f"(x)); return r;
}
__device__ __forceinline__ unsigned ld_acq(const unsigned* p) {
    unsigned v;
    asm volatile("ld.acquire.gpu.u32 %0, [%1];" : "=r"(v) : "l"(p) : "memory");
    return v;
}

// ── single fused kernel: weight tables + Taylor attention + residual + LayerNorm ──
// grid = 16 blocks × 512 threads; block b handles elements [512b, 512b+512)
// (= 4 heads). Batch row = b>>2; the 4 blocks of a row combine LN stats.
__global__ __launch_bounds__(512)
void fused_all(const float* __restrict__ q, const float* __restrict__ k,
               const float* __restrict__ v,
               const float* __restrict__ wq, const float* __restrict__ wk,
               const float* __restrict__ wv, const float* __restrict__ wf,
               const float* __restrict__ lnw, const float* __restrict__ lnb,
               float* __restrict__ out) {
    __shared__ float s_wq[2048], s_wv[2048];
    __shared__ float s_wk[16 * 132], s_wf[16 * 132];
    __shared__ float s_g[16][17];     // [sm][sn] = SCALE * dot(wq_seg sm, wk_seg sn)
    __shared__ float s_gv[16][17];    // [sn][sm] = dot(wv_seg sn, wf_seg sm)
    __shared__ float s_G[NT][16];     // (sum_sm g^n)/n!
    __shared__ float s_Hn[NT][16];    // (sum_sm g^n * gvf)/n!
    __shared__ float s_red[16][NT];
    __shared__ float s_Q[4][NT];
    __shared__ float s_c[4 * NT * 16];
    __shared__ float s_C[4][NT + 3];
    __shared__ float s_l1[16], s_l2[16];
    __shared__ float s_mu, s_rstd;

    int t = threadIdx.x;
    int lane = t & 31, warp = t >> 5;
    int base = blockIdx.x * 512;

    float qv = q[base + t];
    float kv = k[base + t];
    float vv = v[base + t];

    // stage weights (1 float4 per thread per array)
    ((float4*)s_wq)[t] = ((const float4*)wq)[t];
    ((float4*)s_wv)[t] = ((const float4*)wv)[t];
    {
        int rr = t >> 5, dd = (t & 31) << 2;
        *(float4*)(s_wk + rr * 132 + dd) = ((const float4*)wk)[t];
        *(float4*)(s_wf + rr * 132 + dd) = ((const float4*)wf)[t];
    }
    __syncthreads();

    // 512 dot-products, one per thread
    {
        int u = t & 255, i = u >> 4, j = u & 15;
        const float* A = (t < 256) ? (s_wq + i * 128) : (s_wv + i * 128);
        const float* B = (t < 256) ? (s_wk + j * 132) : (s_wf + j * 132);
        float s0 = 0.f, s1 = 0.f, s2 = 0.f, s3 = 0.f;
        #pragma unroll
        for (int d = 0; d < 128; d += 4) {
            s0 = fmaf(A[d + 0], B[d + 0], s0);
            s1 = fmaf(A[d + 1], B[d + 1], s1);
            s2 = fmaf(A[d + 2], B[d + 2], s2);
            s3 = fmaf(A[d + 3], B[d + 3], s3);
        }
        float s = (s0 + s1) + (s2 + s3);
        if (t < 256) s_g[i][j] = s * SCALE;   // [sm][sn]
        else         s_gv[i][j] = s;          // [sn][sm]
    }
    __syncthreads();

    // Gn/Hn tables: thread (sn,sm) for t<256; reduce over sm = low 4 lane bits
    if (t < 256) {
        int sn = t >> 4, sm = t & 15;
        float x  = s_g[sm][sn];
        float gv = s_gv[sn][sm];
        float p = 1.f;
        #pragma unroll
        for (int n = 0; n < NT; n++) {
            float Gs = p, Hs = p * gv;
            #pragma unroll
            for (int o = 1; o < 16; o <<= 1) {
                Gs += __shfl_xor_sync(0xffffffffu, Gs, o);
                Hs += __shfl_xor_sync(0xffffffffu, Hs, o);
            }
            if (sm == 0) {
                s_G[n][sn]  = Gs * c_invfact[n];
                s_Hn[n][sn] = Hs * c_invfact[n];
            }
            p *= x;
        }
    }

    // Qn per head: powers of qv, warp-reduce, cross-warp via smem
    {
        float pw[NT];
        pw[0] = 1.f;
        #pragma unroll
        for (int n = 1; n < NT; n++) pw[n] = pw[n - 1] * qv;
        #pragma unroll
        for (int o = 16; o; o >>= 1) {
            #pragma unroll
            for (int n = 0; n < NT; n++) pw[n] += __shfl_xor_sync(0xffffffffu, pw[n], o);
        }
        if (lane == 0) {
            #pragma unroll
            for (int n = 0; n < NT; n++) s_red[warp][n] = pw[n];
        }
    }
    __syncthreads();

    if (t < 4 * NT) {
        int h = t / NT, n = t - h * NT;
        s_Q[h][n] = (s_red[4 * h][n] + s_red[4 * h + 1][n])
                  + (s_red[4 * h + 2][n] + s_red[4 * h + 3][n]);
    }
    __syncthreads();

    // per-head Horner coefficients c[h][n][sn] = Q[h][n] * Gn[n][sn]
    for (int idx = t; idx < 4 * NT * 16; idx += 512) {
        int h = idx / (NT * 16);
        int rem = idx - h * (NT * 16);
        int n = rem >> 4, sn = rem & 15;
        s_c[idx] = s_Q[h][n] * s_G[n][sn];
    }
    __syncthreads();

    // core: Z[rn,sn] Horner in kv → W = 1/Z; T[n] = sum_sn Hn[sn]*W[sn]
    int h = t >> 7;
    const float* ch = s_c + h * (NT * 16);
    float W[16];
    #pragma unroll
    for (int sn = 0; sn < 16; sn++) {
        float z = ch[(NT - 1) * 16 + sn];
        #pragma unroll
        for (int n = NT - 2; n >= 0; n--) z = fmaf(z, kv, ch[n * 16 + sn]);
        W[sn] = rcpf(z);
    }
    float T[NT];
    #pragma unroll
    for (int n = 0; n < NT; n++) {
        float s = 0.f;
        #pragma unroll
        for (int sn = 0; sn < 16; sn++) s = fmaf(s_Hn[n][sn], W[sn], s);
        T[n] = s;
    }
    float kp = vv;
    #pragma unroll
    for (int n = 0; n < NT; n++) { T[n] *= kp; kp *= kv; }

    // C[n] per head = reduce T over the head's 128 lanes
    #pragma unroll
    for (int o = 16; o; o >>= 1) {
        #pragma unroll
        for (int n = 0; n < NT; n++) T[n] += __shfl_xor_sync(0xffffffffu, T[n], o);
    }
    if (lane == 0) {
        #pragma unroll
        for (int n = 0; n < NT; n++) s_red[warp][n] = T[n];
    }
    __syncthreads();
    if (t < 4 * NT) {
        int hh = t / NT, n = t - hh * NT;
        s_C[hh][n] = (s_red[4 * hh][n] + s_red[4 * hh + 1][n])
                   + (s_red[4 * hh + 2][n] + s_red[4 * hh + 3][n]);
    }
    __syncthreads();

    // attn output + residual (register-resident)
    float r = s_C[h][NT - 1];
    #pragma unroll
    for (int n = NT - 2; n >= 0; n--) r = fmaf(r, qv, s_C[h][n]);
    float x = qv + r;

    // ── LayerNorm: block-partial Σx, Σx² ──
    float s  = x;
    float s2 = x * x;
    #pragma unroll
    for (int o = 16; o; o >>= 1) {
        s  += __shfl_xor_sync(0xffffffffu, s,  o);
        s2 += __shfl_xor_sync(0xffffffffu, s2, o);
    }
    if (lane == 0) { s_l1[warp] = s; s_l2[warp] = s2; }
    __syncthreads();

    int row = blockIdx.x >> 2;
    if (t == 0) {
        float ts = 0.f, ts2 = 0.f;
        #pragma unroll
        for (int w = 0; w < 16; w++) { ts += s_l1[w]; ts2 += s_l2[w]; }
        int bi = blockIdx.x & 3;
        g_sums[row][bi][0] = ts;
        g_sums[row][bi][1] = ts2;
        __threadfence();                       // release partials
        atomicAdd(&g_arrive[row], 1u);

        while (ld_acq(&g_arrive[row]) < 4u) __nanosleep(32);

        float S = 0.f, S2 = 0.f;               // fixed order → deterministic
        #pragma unroll
        for (int j = 0; j < 4; j++) { S += g_sums[row][j][0]; S2 += g_sums[row][j][1]; }
        float mu  = S * (1.f / 2048.f);
        float var = S2 * (1.f / 2048.f) - mu * mu;
        s_mu = mu;
        s_rstd = rsqrtf(var + 1e-5f);

        // replay-safe reset: last consumer zeroes the counters for this row
        unsigned tk = atomicAdd(&g_done[row], 1u);
        if (tk == 3u) { g_arrive[row] = 0u; g_done[row] = 0u; }
    }
    __syncthreads();

    float mu = s_mu, rstd = s_rstd;
    int li = (blockIdx.x & 3) * 512 + t;       // index within the 2048 row
    out[base + t] = (x - mu) * rstd * lnw[li] + lnb[li];
}

extern "C" void kernel_launch(void* const* d_in, const int* in_sizes, int n_in,
                              void* d_out, int out_size) {
    const float* query = (const float*)d_in[0];
    const float* key   = (const float*)d_in[1];
    const float* value = (const float*)d_in[2];
    const float* wq    = (const float*)d_in[3];
    const float* wk    = (const float*)d_in[4];
    const float* wv    = (const float*)d_in[5];
    const float* wf    = (const float*)d_in[6];
    const float* lnw   = (const float*)d_in[7];
    const float* lnb   = (const float*)d_in[8];
    float* out = (float*)d_out;

    fused_all<<<16, 512>>>(query, key, value, wq, wk, wv, wf, lnw, lnb, out);
}

// round 10
// speedup vs baseline: 5.5091x; 1.0390x over previous
#include <cuda_runtime.h>

#define NT 9               // Taylor terms n = 0..8
#define SCALE 0.35355339059327373f

// grid-wide table handoff (16 producers -> 32 consumers), replay-safe reset
__device__ float    g_Gn[16 * 12];   // [sn][n] padded to 12; (sum_sm g^n)/n!
__device__ float    g_Hn[16 * 12];   // (sum_sm g^n * gvf)/n!
__device__ unsigned g_tbl_arrive;
__device__ unsigned g_tbl_done;

// cross-block LN reduction (8 blocks per batch row)
__device__ float    g_sums[4][8][2];
__device__ unsigned g_arrive[4];
__device__ unsigned g_done[4];

__constant__ float c_invfact[NT] = {
    1.0f, 1.0f, 0.5f, 1.0f/6.0f, 1.0f/24.0f, 1.0f/120.0f, 1.0f/720.0f,
    1.0f/5040.0f, 1.0f/40320.0f
};

__device__ __forceinline__ float rcpf(float x) {
    float r; asm("rcp.approx.ftz.f32 %0, %1;" : "=f"(r) : "f"(x)); return r;
}
__device__ __forceinline__ unsigned ld_acq(const unsigned* p) {
    unsigned v;
    asm volatile("ld.acquire.gpu.u32 %0, [%1];" : "=r"(v) : "l"(p) : "memory");
    return v;
}

// grid = 32 blocks x 256 threads; block b owns elements [256b, 256b+256) = 2 heads.
// Blocks 0..15 additionally produce table column sn = b.
__global__ __launch_bounds__(256)
void fused_all(const float* __restrict__ q, const float* __restrict__ k,
               const float* __restrict__ v,
               const float* __restrict__ wq, const float* __restrict__ wk,
               const float* __restrict__ wv, const float* __restrict__ wf,
               const float* __restrict__ lnw, const float* __restrict__ lnb,
               float* __restrict__ out) {
    __shared__ float s_G[16][12];     // staged Gn, [sn][n]
    __shared__ float s_H[16][12];     // staged Hn
    __shared__ float s_c[2][16][12];  // Q[h][n] * Gn[sn][n]
    __shared__ float s_Q[2][12];      // per-head sum of qv^n (pads zero)
    __shared__ float s_red[8][9];     // per-warp reduction slots
    __shared__ float s_C[2][12];
    __shared__ float s_colg[16], s_colv[16];
    __shared__ float s_l1[8], s_l2[8];
    __shared__ float s_mu, s_rstd;

    const int t = threadIdx.x;
    const int lane = t & 31, warp = t >> 5;
    const int blk = blockIdx.x;
    const int base = blk * 256;

    const float qv = q[base + t];
    const float kv = k[base + t];
    const float vv = v[base + t];

    // ── producer: compute table column sn = blk (blocks 0..15) ──
    if (blk < 16) {
        const int col = blk;
        const int sm = t >> 4, dp = t & 15;          // 16 threads per dot
        {
            const float* A = wq + sm * 128 + dp * 8;
            const float* B = wk + col * 128 + dp * 8;
            float s = 0.f;
            #pragma unroll
            for (int d = 0; d < 8; d++) s = fmaf(A[d], B[d], s);
            #pragma unroll
            for (int o = 8; o; o >>= 1) s += __shfl_xor_sync(0xffffffffu, s, o);
            if (dp == 0) s_colg[sm] = s * SCALE;     // g[sm][col]
        }
        {
            const float* A = wv + col * 128 + dp * 8;
            const float* B = wf + sm * 128 + dp * 8;
            float s = 0.f;
            #pragma unroll
            for (int d = 0; d < 8; d++) s = fmaf(A[d], B[d], s);
            #pragma unroll
            for (int o = 8; o; o >>= 1) s += __shfl_xor_sync(0xffffffffu, s, o);
            if (dp == 0) s_colv[sm] = s;             // gv[col][sm]
        }
        __syncthreads();
        if (t < 16) {                                // lanes 0..15 of warp 0
            float x  = s_colg[t];
            float gv = s_colv[t];
            float p = 1.f;
            #pragma unroll
            for (int n = 0; n < NT; n++) {
                float Gs = p, Hs = p * gv;
                #pragma unroll
                for (int o = 8; o; o >>= 1) {
                    Gs += __shfl_xor_sync(0x0000ffffu, Gs, o);
                    Hs += __shfl_xor_sync(0x0000ffffu, Hs, o);
                }
                if (t == 0) {
                    g_Gn[col * 12 + n] = Gs * c_invfact[n];
                    g_Hn[col * 12 + n] = Hs * c_invfact[n];
                }
                p *= x;
            }
        }
        if (t == 0) { __threadfence(); atomicAdd(&g_tbl_arrive, 1u); }
    }

    // ── Qn per head (overlaps producer skew): qv^1..qv^8 ──
    // plain reductions cover lane bits 4,3; halving stages cover bits 2,1,0.
    {
        float pv[8];
        pv[0] = qv;
        #pragma unroll
        for (int i = 1; i < 8; i++) pv[i] = pv[i - 1] * qv;
        #pragma unroll
        for (int o = 16; o >= 8; o >>= 1) {
            #pragma unroll
            for (int i = 0; i < 8; i++) pv[i] += __shfl_xor_sync(0xffffffffu, pv[i], o);
        }
        #pragma unroll
        for (int r = 0; r < 4; r++) {
            float lo = pv[r], hi = pv[r + 4];
            float keep = (lane & 4) ? hi : lo, send = (lane & 4) ? lo : hi;
            pv[r] = keep + __shfl_xor_sync(0xffffffffu, send, 4);
        }
        #pragma unroll
        for (int r = 0; r < 2; r++) {
            float lo = pv[r], hi = pv[r + 2];
            float keep = (lane & 2) ? hi : lo, send = (lane & 2) ? lo : hi;
            pv[r] = keep + __shfl_xor_sync(0xffffffffu, send, 2);
        }
        {
            float lo = pv[0], hi = pv[1];
            float keep = (lane & 1) ? hi : lo, send = (lane & 1) ? lo : hi;
            pv[0] = keep + __shfl_xor_sync(0xffffffffu, send, 1);
        }
        if (lane < 8) s_red[warp][lane] = pv[0];     // = sum_warp qv^{lane+1}
    }
    __syncthreads();
    if (t < 16) {
        int h = t >> 3, n = t & 7;
        s_Q[h][n + 1] = (s_red[4 * h][n] + s_red[4 * h + 1][n])
                      + (s_red[4 * h + 2][n] + s_red[4 * h + 3][n]);
    }
    if (t < 2) { s_Q[t][0] = 128.f; s_Q[t][9] = 0.f; s_Q[t][10] = 0.f; s_Q[t][11] = 0.f; }

    // ── grid sync: wait for all 16 table columns ──
    if (t == 0) { while (ld_acq(&g_tbl_arrive) < 16u) __nanosleep(20); }
    __syncthreads();

    // stage tables from L2 (pads zeroed)
    if (t < 192) {
        int n = t % 12;
        float gn = (n < NT) ? __ldcg(&g_Gn[t]) : 0.f;
        float hn = (n < NT) ? __ldcg(&g_Hn[t]) : 0.f;
        ((float*)s_G)[t] = gn;
        ((float*)s_H)[t] = hn;
    }
    __syncthreads();
    if (t == 0) {   // replay-safe reset of table counters (all blocks past the spin)
        unsigned tk = atomicAdd(&g_tbl_done, 1u);
        if (tk == 31u) { g_tbl_arrive = 0u; g_tbl_done = 0u; }
    }

    // per-head Horner coefficients c[h][sn][n] = Q[h][n] * Gn[sn][n]
    for (int idx = t; idx < 384; idx += 256) {
        int h = idx / 192, rem = idx - h * 192;
        int sn = rem / 12, n = rem - sn * 12;
        s_c[h][sn][n] = s_Q[h][n] * s_G[sn][n];
    }
    __syncthreads();

    // ── core: per rn, Z[sn] Horner in kv -> 1/Z; accumulate T[n] ──
    const int h = t >> 7;
    const float* cb = &s_c[h][0][0];
    float T[9];
    #pragma unroll
    for (int n = 0; n < 9; n++) T[n] = 0.f;

    #pragma unroll 4
    for (int sn = 0; sn < 16; sn++) {
        float4 a0 = *(const float4*)(cb + sn * 12);
        float4 a1 = *(const float4*)(cb + sn * 12 + 4);
        float  a8 = cb[sn * 12 + 8];
        float z = a8;
        z = fmaf(z, kv, a1.w);
        z = fmaf(z, kv, a1.z);
        z = fmaf(z, kv, a1.y);
        z = fmaf(z, kv, a1.x);
        z = fmaf(z, kv, a0.w);
        z = fmaf(z, kv, a0.z);
        z = fmaf(z, kv, a0.y);
        z = fmaf(z, kv, a0.x);
        float W = rcpf(z);
        float4 h0 = *(const float4*)(&s_H[sn][0]);
        float4 h1 = *(const float4*)(&s_H[sn][4]);
        float  h8 = s_H[sn][8];
        T[0] = fmaf(h0.x, W, T[0]);
        T[1] = fmaf(h0.y, W, T[1]);
        T[2] = fmaf(h0.z, W, T[2]);
        T[3] = fmaf(h0.w, W, T[3]);
        T[4] = fmaf(h1.x, W, T[4]);
        T[5] = fmaf(h1.y, W, T[5]);
        T[6] = fmaf(h1.z, W, T[6]);
        T[7] = fmaf(h1.w, W, T[7]);
        T[8] = fmaf(h8,   W, T[8]);
    }
    {
        float kp = vv;
        #pragma unroll
        for (int n = 0; n < 9; n++) { T[n] *= kp; kp *= kv; }
    }

    // warp-reduce 16 (padded) values via halving over bits 4..1, then the
    // FINAL bit-0 stage (R7 bug: this stage was missing -> odd lanes dropped).
    {
        float rv[16];
        #pragma unroll
        for (int i = 0; i < 9; i++) rv[i] = T[i];
        #pragma unroll
        for (int i = 9; i < 16; i++) rv[i] = 0.f;
        #pragma unroll
        for (int r = 0; r < 8; r++) {
            float lo = rv[r], hi = rv[r + 8];
            float keep = (lane & 16) ? hi : lo, send = (lane & 16) ? lo : hi;
            rv[r] = keep + __shfl_xor_sync(0xffffffffu, send, 16);
        }
        #pragma unroll
        for (int r = 0; r < 4; r++) {
            float lo = rv[r], hi = rv[r + 4];
            float keep = (lane & 8) ? hi : lo, send = (lane & 8) ? lo : hi;
            rv[r] = keep + __shfl_xor_sync(0xffffffffu, send, 8);
        }
        #pragma unroll
        for (int r = 0; r < 2; r++) {
            float lo = rv[r], hi = rv[r + 2];
            float keep = (lane & 4) ? hi : lo, send = (lane & 4) ? lo : hi;
            rv[r] = keep + __shfl_xor_sync(0xffffffffu, send, 4);
        }
        {
            float lo = rv[0], hi = rv[1];
            float keep = (lane & 2) ? hi : lo, send = (lane & 2) ? lo : hi;
            rv[0] = keep + __shfl_xor_sync(0xffffffffu, send, 2);
        }
        rv[0] += __shfl_xor_sync(0xffffffffu, rv[0], 1);   // complete 32-lane sum
        int j = lane >> 1;
        if (((lane & 1) == 0) && j < 9) s_red[warp][j] = rv[0];
    }
    __syncthreads();
    if (t < 18) {
        int hh = t / 9, n = t - hh * 9;
        s_C[hh][n] = (s_red[4 * hh][n] + s_red[4 * hh + 1][n])
                   + (s_red[4 * hh + 2][n] + s_red[4 * hh + 3][n]);
    }
    __syncthreads();

    // out[rm] = sum_n qv^n * C[n] (Horner), + residual
    float r = s_C[h][8];
    #pragma unroll
    for (int n = 7; n >= 0; n--) r = fmaf(r, qv, s_C[h][n]);
    float x = qv + r;

    // ── LayerNorm across the 2048-row (8 blocks) ──
    float s1 = x, s2 = x * x;
    #pragma unroll
    for (int o = 16; o; o >>= 1) {
        s1 += __shfl_xor_sync(0xffffffffu, s1, o);
        s2 += __shfl_xor_sync(0xffffffffu, s2, o);
    }
    if (lane == 0) { s_l1[warp] = s1; s_l2[warp] = s2; }
    __syncthreads();

    const int row = blk >> 3, bi = blk & 7;
    if (t == 0) {
        float ts = 0.f, ts2 = 0.f;
        #pragma unroll
        for (int w = 0; w < 8; w++) { ts += s_l1[w]; ts2 += s_l2[w]; }
        g_sums[row][bi][0] = ts;
        g_sums[row][bi][1] = ts2;
        __threadfence();
        atomicAdd(&g_arrive[row], 1u);
        while (ld_acq(&g_arrive[row]) < 8u) __nanosleep(20);

        float S = 0.f, S2 = 0.f;              // fixed order -> deterministic
        #pragma unroll
        for (int j = 0; j < 8; j++) { S += g_sums[row][j][0]; S2 += g_sums[row][j][1]; }
        float mu  = S * (1.f / 2048.f);
        float var = S2 * (1.f / 2048.f) - mu * mu;
        s_mu = mu;
        s_rstd = rsqrtf(var + 1e-5f);

        unsigned tk = atomicAdd(&g_done[row], 1u);
        if (tk == 7u) { g_arrive[row] = 0u; g_done[row] = 0u; }
    }
    __syncthreads();

    const int li = bi * 256 + t;
    out[base + t] = (x - s_mu) * s_rstd * lnw[li] + lnb[li];
}

extern "C" void kernel_launch(void* const* d_in, const int* in_sizes, int n_in,
                              void* d_out, int out_size) {
    const float* query = (const float*)d_in[0];
    const float* key   = (const float*)d_in[1];
    const float* value = (const float*)d_in[2];
    const float* wq    = (const float*)d_in[3];
    const float* wk    = (const float*)d_in[4];
    const float* wv    = (const float*)d_in[5];
    const float* wf    = (const float*)d_in[6];
    const float* lnw   = (const float*)d_in[7];
    const float* lnb   = (const float*)d_in[8];
    float* out = (float*)d_out;

    fused_all<<<32, 256>>>(query, key, value, wq, wk, wv, wf, lnw, lnb, out);
}

// round 12
// speedup vs baseline: 6.1657x; 1.1192x over previous
#include <cuda_runtime.h>
#include <cstdint>

#define NT 9               // Taylor terms n = 0..8
#define SCALE 0.35355339059327373f

__constant__ float c_invfact[NT] = {
    1.0f, 1.0f, 0.5f, 1.0f/6.0f, 1.0f/24.0f, 1.0f/120.0f, 1.0f/720.0f,
    1.0f/5040.0f, 1.0f/40320.0f
};

__device__ __forceinline__ float rcpf(float x) {
    float r; asm("rcp.approx.ftz.f32 %0, %1;" : "=f"(r) : "f"(x)); return r;
}
__device__ __forceinline__ uint32_t smem_u32(const void* p) {
    return (uint32_t)__cvta_generic_to_shared(p);
}
__device__ __forceinline__ float dsmem_ld(uint32_t laddr, uint32_t rank) {
    uint32_t ra; float v;
    asm("mapa.shared::cluster.u32 %0, %1, %2;" : "=r"(ra) : "r"(laddr), "r"(rank));
    asm volatile("ld.shared::cluster.f32 %0, [%1];" : "=f"(v) : "r"(ra));
    return v;
}
#define CLUSTER_SYNC() do { \
    asm volatile("barrier.cluster.arrive.aligned;" ::: "memory"); \
    asm volatile("barrier.cluster.wait.aligned;" ::: "memory"); } while (0)

// 32 CTAs x 256 threads, clusters of 8 (one cluster per 2048-row).
// CTA handles elements [256*blk, 256*blk+256) = 2 heads; produces table cols 2r, 2r+1.
__global__ __launch_bounds__(256) __cluster_dims__(8, 1, 1)
void fused_all(const float* __restrict__ q, const float* __restrict__ k,
               const float* __restrict__ v,
               const float* __restrict__ wq, const float* __restrict__ wk,
               const float* __restrict__ wv, const float* __restrict__ wf,
               const float* __restrict__ lnw, const float* __restrict__ lnb,
               float* __restrict__ out) {
    __shared__ __align__(16) float s_G[16][12];   // (sum_sm g^n)/n!      [sn][n]
    __shared__ __align__(16) float s_H[16][12];   // (sum_sm g^n gvf)/n!  [sn][n]
    __shared__ __align__(16) float s_c[2][16][12];
    __shared__ float s_Q[2][12];
    __shared__ float s_red[8][9];
    __shared__ float s_C[2][12];
    __shared__ float s_colg[2][16], s_colv[2][16];
    __shared__ float s_l1[8], s_l2[8];
    __shared__ float s_lnp[2];
    __shared__ float s_mu, s_rstd;

    const int t = threadIdx.x;
    const int lane = t & 31, warp = t >> 5;
    const int blk = blockIdx.x, rank = blk & 7;
    const int base = blk * 256;

    const float qv = q[base + t];
    const float kv = k[base + t];
    const float vv = v[base + t];

    // ── produce table columns col = 2*rank + (t>=128): 8 threads per dot, float4 loads ──
    {
        const int grp = t >> 7;
        const int col = rank * 2 + grp;
        const int u = t & 127, sm = u >> 3, dp = u & 7;
        const float4* Aq = (const float4*)(wq + sm * 128 + dp * 16);
        const float4* Bk = (const float4*)(wk + col * 128 + dp * 16);
        const float4* Av = (const float4*)(wv + col * 128 + dp * 16);
        const float4* Bf = (const float4*)(wf + sm * 128 + dp * 16);
        float sg = 0.f, sv = 0.f;
        #pragma unroll
        for (int j = 0; j < 4; j++) {
            float4 a = Aq[j], b = Bk[j];
            sg = fmaf(a.x, b.x, sg); sg = fmaf(a.y, b.y, sg);
            sg = fmaf(a.z, b.z, sg); sg = fmaf(a.w, b.w, sg);
            float4 c2 = Av[j], d2 = Bf[j];
            sv = fmaf(c2.x, d2.x, sv); sv = fmaf(c2.y, d2.y, sv);
            sv = fmaf(c2.z, d2.z, sv); sv = fmaf(c2.w, d2.w, sv);
        }
        #pragma unroll
        for (int o = 4; o; o >>= 1) {
            sg += __shfl_xor_sync(0xffffffffu, sg, o);
            sv += __shfl_xor_sync(0xffffffffu, sv, o);
        }
        if (dp == 0) { s_colg[grp][sm] = sg * SCALE; s_colv[grp][sm] = sv; }
    }
    __syncthreads();

    // powers + per-column sums (warp 0: two 16-lane groups, one per column)
    if (t < 32) {
        const int ci = t >> 4, sm = t & 15, col = rank * 2 + ci;
        float x  = s_colg[ci][sm];
        float gv = s_colv[ci][sm];
        float p = 1.f;
        #pragma unroll
        for (int n = 0; n < NT; n++) {
            float Gs = p, Hs = p * gv;
            #pragma unroll
            for (int o = 8; o; o >>= 1) {
                Gs += __shfl_xor_sync(0xffffffffu, Gs, o);
                Hs += __shfl_xor_sync(0xffffffffu, Hs, o);
            }
            if (sm == 0) {
                s_G[col][n] = Gs * c_invfact[n];
                s_H[col][n] = Hs * c_invfact[n];
            }
            p *= x;
        }
    }

    // ── Qn per head: qv^1..qv^8 (bits 4,3 plain; 2,1,0 halving) ──
    {
        float pv[8];
        pv[0] = qv;
        #pragma unroll
        for (int i = 1; i < 8; i++) pv[i] = pv[i - 1] * qv;
        #pragma unroll
        for (int o = 16; o >= 8; o >>= 1) {
            #pragma unroll
            for (int i = 0; i < 8; i++) pv[i] += __shfl_xor_sync(0xffffffffu, pv[i], o);
        }
        #pragma unroll
        for (int r = 0; r < 4; r++) {
            float lo = pv[r], hi = pv[r + 4];
            float keep = (lane & 4) ? hi : lo, send = (lane & 4) ? lo : hi;
            pv[r] = keep + __shfl_xor_sync(0xffffffffu, send, 4);
        }
        #pragma unroll
        for (int r = 0; r < 2; r++) {
            float lo = pv[r], hi = pv[r + 2];
            float keep = (lane & 2) ? hi : lo, send = (lane & 2) ? lo : hi;
            pv[r] = keep + __shfl_xor_sync(0xffffffffu, send, 2);
        }
        {
            float lo = pv[0], hi = pv[1];
            float keep = (lane & 1) ? hi : lo, send = (lane & 1) ? lo : hi;
            pv[0] = keep + __shfl_xor_sync(0xffffffffu, send, 1);
        }
        if (lane < 8) s_red[warp][lane] = pv[0];     // sum_warp qv^{lane+1}
    }
    __syncthreads();
    if (t < 16) {
        int h = t >> 3, n = t & 7;
        s_Q[h][n + 1] = (s_red[4 * h][n] + s_red[4 * h + 1][n])
                      + (s_red[4 * h + 2][n] + s_red[4 * h + 3][n]);
    }
    if (t < 2) s_Q[t][0] = 128.f;
    __syncthreads();   // own table cols + s_Q visible CTA-wide before cluster barrier

    // ── cluster exchange: gather the other 14 columns via DSMEM ──
    CLUSTER_SYNC();
    for (int idx = t; idx < 288; idx += 256) {       // 2 arrays x 16 cols x 9 terms
        int a = idx / 144, rem = idx - a * 144;
        int col = rem / 9, n = rem - col * 9;
        int rk = col >> 1;
        if (rk != rank) {
            float* dst = a ? &s_H[col][n] : &s_G[col][n];
            *dst = dsmem_ld(smem_u32(dst), (uint32_t)rk);
        }
    }
    __syncthreads();

    // per-head Horner coefficients c[h][sn][n] = Q[h][n] * Gn[sn][n]
    for (int idx = t; idx < 288; idx += 256) {
        int h2 = idx / 144, rem = idx - h2 * 144;
        int sn = rem / 9, n = rem - sn * 9;
        s_c[h2][sn][n] = s_Q[h2][n] * s_G[sn][n];
    }
    __syncthreads();

    // ── core: per rn, Z[sn] Horner in kv -> 1/Z; accumulate T[n] ──
    const int h = t >> 7;
    const float* cb = &s_c[h][0][0];
    float T[9];
    #pragma unroll
    for (int n = 0; n < 9; n++) T[n] = 0.f;

    #pragma unroll 4
    for (int sn = 0; sn < 16; sn++) {
        float4 a0 = *(const float4*)(cb + sn * 12);
        float4 a1 = *(const float4*)(cb + sn * 12 + 4);
        float  a8 = cb[sn * 12 + 8];
        float z = a8;
        z = fmaf(z, kv, a1.w);
        z = fmaf(z, kv, a1.z);
        z = fmaf(z, kv, a1.y);
        z = fmaf(z, kv, a1.x);
        z = fmaf(z, kv, a0.w);
        z = fmaf(z, kv, a0.z);
        z = fmaf(z, kv, a0.y);
        z = fmaf(z, kv, a0.x);
        float W = rcpf(z);
        float4 h0 = *(const float4*)(&s_H[sn][0]);
        float4 h1 = *(const float4*)(&s_H[sn][4]);
        float  h8 = s_H[sn][8];
        T[0] = fmaf(h0.x, W, T[0]);
        T[1] = fmaf(h0.y, W, T[1]);
        T[2] = fmaf(h0.z, W, T[2]);
        T[3] = fmaf(h0.w, W, T[3]);
        T[4] = fmaf(h1.x, W, T[4]);
        T[5] = fmaf(h1.y, W, T[5]);
        T[6] = fmaf(h1.z, W, T[6]);
        T[7] = fmaf(h1.w, W, T[7]);
        T[8] = fmaf(h8,   W, T[8]);
    }
    {
        float kp = vv;
        #pragma unroll
        for (int n = 0; n < 9; n++) { T[n] *= kp; kp *= kv; }
    }

    // warp-reduce 16 (padded) values: halving over bits 4..1 + final bit-0 stage
    {
        float rv[16];
        #pragma unroll
        for (int i = 0; i < 9; i++) rv[i] = T[i];
        #pragma unroll
        for (int i = 9; i < 16; i++) rv[i] = 0.f;
        #pragma unroll
        for (int r = 0; r < 8; r++) {
            float lo = rv[r], hi = rv[r + 8];
            float keep = (lane & 16) ? hi : lo, send = (lane & 16) ? lo : hi;
            rv[r] = keep + __shfl_xor_sync(0xffffffffu, send, 16);
        }
        #pragma unroll
        for (int r = 0; r < 4; r++) {
            float lo = rv[r], hi = rv[r + 4];
            float keep = (lane & 8) ? hi : lo, send = (lane & 8) ? lo : hi;
            rv[r] = keep + __shfl_xor_sync(0xffffffffu, send, 8);
        }
        #pragma unroll
        for (int r = 0; r < 2; r++) {
            float lo = rv[r], hi = rv[r + 2];
            float keep = (lane & 4) ? hi : lo, send = (lane & 4) ? lo : hi;
            rv[r] = keep + __shfl_xor_sync(0xffffffffu, send, 4);
        }
        {
            float lo = rv[0], hi = rv[1];
            float keep = (lane & 2) ? hi : lo, send = (lane & 2) ? lo : hi;
            rv[0] = keep + __shfl_xor_sync(0xffffffffu, send, 2);
        }
        rv[0] += __shfl_xor_sync(0xffffffffu, rv[0], 1);
        int j = lane >> 1;
        if (((lane & 1) == 0) && j < 9) s_red[warp][j] = rv[0];
    }
    __syncthreads();
    if (t < 18) {
        int hh = t / 9, n = t - hh * 9;
        s_C[hh][n] = (s_red[4 * hh][n] + s_red[4 * hh + 1][n])
                   + (s_red[4 * hh + 2][n] + s_red[4 * hh + 3][n]);
    }
    __syncthreads();

    // out[rm] = sum_n qv^n * C[n] (Horner), + residual
    float r = s_C[h][8];
    #pragma unroll
    for (int n = 7; n >= 0; n--) r = fmaf(r, qv, s_C[h][n]);
    const float x = qv + r;

    // ── LayerNorm across the 2048-row via cluster DSMEM ──
    float s1 = x, s2 = x * x;
    #pragma unroll
    for (int o = 16; o; o >>= 1) {
        s1 += __shfl_xor_sync(0xffffffffu, s1, o);
        s2 += __shfl_xor_sync(0xffffffffu, s2, o);
    }
    if (lane == 0) { s_l1[warp] = s1; s_l2[warp] = s2; }
    __syncthreads();
    if (t == 0) {
        float ts = 0.f, ts2 = 0.f;
        #pragma unroll
        for (int w = 0; w < 8; w++) { ts += s_l1[w]; ts2 += s_l2[w]; }
        s_lnp[0] = ts;
        s_lnp[1] = ts2;
    }
    __syncthreads();
    CLUSTER_SYNC();                       // partials visible cluster-wide
    if (t < 8) {                          // parallel remote gather
        s_l1[t] = dsmem_ld(smem_u32(&s_lnp[0]), (uint32_t)t);
        s_l2[t] = dsmem_ld(smem_u32(&s_lnp[1]), (uint32_t)t);
    }
    __syncthreads();
    if (t == 0) {
        float S = 0.f, S2 = 0.f;          // fixed order -> deterministic
        #pragma unroll
        for (int j = 0; j < 8; j++) { S += s_l1[j]; S2 += s_l2[j]; }
        float mu  = S * (1.f / 2048.f);
        float var = S2 * (1.f / 2048.f) - mu * mu;
        s_mu = mu;
        s_rstd = rsqrtf(var + 1e-5f);
    }
    __syncthreads();

    const int li = rank * 256 + t;        // index within the 2048 row
    out[base + t] = (x - s_mu) * s_rstd * lnw[li] + lnb[li];

    CLUSTER_SYNC();                       // keep smem alive for peers' DSMEM reads
}

extern "C" void kernel_launch(void* const* d_in, const int* in_sizes, int n_in,
                              void* d_out, int out_size) {
    const float* query = (const float*)d_in[0];
    const float* key   = (const float*)d_in[1];
    const float* value = (const float*)d_in[2];
    const float* wq    = (const float*)d_in[3];
    const float* wk    = (const float*)d_in[4];
    const float* wv    = (const float*)d_in[5];
    const float* wf    = (const float*)d_in[6];
    const float* lnw   = (const float*)d_in[7];
    const float* lnb   = (const float*)d_in[8];
    float* out = (float*)d_out;

    fused_all<<<32, 256>>>(query, key, value, wq, wk, wv, wf, lnw, lnb, out);
}

// round 14
// speedup vs baseline: 6.4468x; 1.0456x over previous
#include <cuda_runtime.h>
#include <cstdint>

#define NT 9               // Taylor terms n = 0..8
#define SCALE 0.35355339059327373f

__constant__ float c_invfact[NT] = {
    1.0f, 1.0f, 0.5f, 1.0f/6.0f, 1.0f/24.0f, 1.0f/120.0f, 1.0f/720.0f,
    1.0f/5040.0f, 1.0f/40320.0f
};

__device__ __forceinline__ float rcpf(float x) {
    float r; asm("rcp.approx.ftz.f32 %0, %1;" : "=f"(r) : "f"(x)); return r;
}
__device__ __forceinline__ uint32_t smem_u32(const void* p) {
    return (uint32_t)__cvta_generic_to_shared(p);
}
__device__ __forceinline__ float dsmem_ld(uint32_t laddr, uint32_t rank) {
    uint32_t ra; float v;
    asm("mapa.shared::cluster.u32 %0, %1, %2;" : "=r"(ra) : "r"(laddr), "r"(rank));
    asm volatile("ld.shared::cluster.f32 %0, [%1];" : "=f"(v) : "r"(ra));
    return v;
}
#define CLUSTER_SYNC() do { \
    asm volatile("barrier.cluster.arrive.aligned;" ::: "memory"); \
    asm volatile("barrier.cluster.wait.aligned;" ::: "memory"); } while (0)

// 32 CTAs x 256 threads, clusters of 8 (one cluster per 2048-row).
// CTA handles elements [256*blk, 256*blk+256) = 2 heads; produces table cols 2r, 2r+1.
__global__ __launch_bounds__(256) __cluster_dims__(8, 1, 1)
void fused_all(const float* __restrict__ q, const float* __restrict__ k,
               const float* __restrict__ v,
               const float* __restrict__ wq, const float* __restrict__ wk,
               const float* __restrict__ wv, const float* __restrict__ wf,
               const float* __restrict__ lnw, const float* __restrict__ lnb,
               float* __restrict__ out) {
    __shared__ __align__(16) float s_G[16][12];   // (sum_sm g^n)/n!      [sn][n]
    __shared__ __align__(16) float s_H[16][12];   // (sum_sm g^n gvf)/n!  [sn][n]
    __shared__ __align__(16) float s_c[2][16][12];
    __shared__ float s_Q[2][12];
    __shared__ float s_red[8][9];
    __shared__ float s_C[2][12];
    __shared__ float s_colg[2][16], s_colv[2][16];
    __shared__ float s_l1[8], s_l2[8];
    __shared__ float s_lnp[2];

    const int t = threadIdx.x;
    const int lane = t & 31, warp = t >> 5;
    const int blk = blockIdx.x, rank = blk & 7;
    const int base = blk * 256;
    const int li = rank * 256 + t;        // index within the 2048 row

    // prefetch ALL gmem inputs up-front (MLP overlap; hides the LN-tail DRAM latency)
    const float qv = q[base + t];
    const float kv = k[base + t];
    const float vv = v[base + t];
    const float wl = lnw[li];
    const float bl = lnb[li];

    // ── produce table columns col = 2*rank + (t>=128): 8 threads per dot, float4 loads ──
    {
        const int grp = t >> 7;
        const int col = rank * 2 + grp;
        const int u = t & 127, sm = u >> 3, dp = u & 7;
        const float4* Aq = (const float4*)(wq + sm * 128 + dp * 16);
        const float4* Bk = (const float4*)(wk + col * 128 + dp * 16);
        const float4* Av = (const float4*)(wv + col * 128 + dp * 16);
        const float4* Bf = (const float4*)(wf + sm * 128 + dp * 16);
        float sg = 0.f, sv = 0.f;
        #pragma unroll
        for (int j = 0; j < 4; j++) {
            float4 a = Aq[j], b = Bk[j];
            sg = fmaf(a.x, b.x, sg); sg = fmaf(a.y, b.y, sg);
            sg = fmaf(a.z, b.z, sg); sg = fmaf(a.w, b.w, sg);
            float4 c2 = Av[j], d2 = Bf[j];
            sv = fmaf(c2.x, d2.x, sv); sv = fmaf(c2.y, d2.y, sv);
            sv = fmaf(c2.z, d2.z, sv); sv = fmaf(c2.w, d2.w, sv);
        }
        #pragma unroll
        for (int o = 4; o; o >>= 1) {
            sg += __shfl_xor_sync(0xffffffffu, sg, o);
            sv += __shfl_xor_sync(0xffffffffu, sv, o);
        }
        if (dp == 0) { s_colg[grp][sm] = sg * SCALE; s_colv[grp][sm] = sv; }
    }
    __syncthreads();

    // powers + per-column sums (warp 0: two 16-lane groups, one per column)
    if (t < 32) {
        const int ci = t >> 4, sm = t & 15, col = rank * 2 + ci;
        float x  = s_colg[ci][sm];
        float gv = s_colv[ci][sm];
        float p = 1.f;
        #pragma unroll
        for (int n = 0; n < NT; n++) {
            float Gs = p, Hs = p * gv;
            #pragma unroll
            for (int o = 8; o; o >>= 1) {
                Gs += __shfl_xor_sync(0xffffffffu, Gs, o);
                Hs += __shfl_xor_sync(0xffffffffu, Hs, o);
            }
            if (sm == 0) {
                s_G[col][n] = Gs * c_invfact[n];
                s_H[col][n] = Hs * c_invfact[n];
            }
            p *= x;
        }
    }

    // ── Qn per head: qv^1..qv^8 (bits 4,3 plain; 2,1,0 halving) ──
    {
        float pv[8];
        pv[0] = qv;
        #pragma unroll
        for (int i = 1; i < 8; i++) pv[i] = pv[i - 1] * qv;
        #pragma unroll
        for (int o = 16; o >= 8; o >>= 1) {
            #pragma unroll
            for (int i = 0; i < 8; i++) pv[i] += __shfl_xor_sync(0xffffffffu, pv[i], o);
        }
        #pragma unroll
        for (int r = 0; r < 4; r++) {
            float lo = pv[r], hi = pv[r + 4];
            float keep = (lane & 4) ? hi : lo, send = (lane & 4) ? lo : hi;
            pv[r] = keep + __shfl_xor_sync(0xffffffffu, send, 4);
        }
        #pragma unroll
        for (int r = 0; r < 2; r++) {
            float lo = pv[r], hi = pv[r + 2];
            float keep = (lane & 2) ? hi : lo, send = (lane & 2) ? lo : hi;
            pv[r] = keep + __shfl_xor_sync(0xffffffffu, send, 2);
        }
        {
            float lo = pv[0], hi = pv[1];
            float keep = (lane & 1) ? hi : lo, send = (lane & 1) ? lo : hi;
            pv[0] = keep + __shfl_xor_sync(0xffffffffu, send, 1);
        }
        if (lane < 8) s_red[warp][lane] = pv[0];     // sum_warp qv^{lane+1}
    }
    __syncthreads();
    if (t < 16) {
        int h = t >> 3, n = t & 7;
        s_Q[h][n + 1] = (s_red[4 * h][n] + s_red[4 * h + 1][n])
                      + (s_red[4 * h + 2][n] + s_red[4 * h + 3][n]);
    }
    if (t < 2) s_Q[t][0] = 128.f;
    // no __syncthreads here: warp0's s_G/s_H writes precede its own cluster-arrive
    // (peer visibility via the barrier); s_Q visibility is covered by the
    // post-gather __syncthreads below.

    // ── cluster exchange: gather the other 14 columns via DSMEM ──
    CLUSTER_SYNC();
    for (int idx = t; idx < 288; idx += 256) {       // 2 arrays x 16 cols x 9 terms
        int a = idx / 144, rem = idx - a * 144;
        int col = rem / 9, n = rem - col * 9;
        int rk = col >> 1;
        if (rk != rank) {
            float* dst = a ? &s_H[col][n] : &s_G[col][n];
            *dst = dsmem_ld(smem_u32(dst), (uint32_t)rk);
        }
    }
    __syncthreads();

    // per-head Horner coefficients c[h][sn][n] = Q[h][n] * Gn[sn][n]
    for (int idx = t; idx < 288; idx += 256) {
        int h2 = idx / 144, rem = idx - h2 * 144;
        int sn = rem / 9, n = rem - sn * 9;
        s_c[h2][sn][n] = s_Q[h2][n] * s_G[sn][n];
    }
    __syncthreads();

    // ── core: per rn, Z[sn] Horner in kv -> 1/Z; accumulate T[n] ──
    const int h = t >> 7;
    const float* cb = &s_c[h][0][0];
    float T[9];
    #pragma unroll
    for (int n = 0; n < 9; n++) T[n] = 0.f;

    #pragma unroll 4
    for (int sn = 0; sn < 16; sn++) {
        float4 a0 = *(const float4*)(cb + sn * 12);
        float4 a1 = *(const float4*)(cb + sn * 12 + 4);
        float  a8 = cb[sn * 12 + 8];
        float z = a8;
        z = fmaf(z, kv, a1.w);
        z = fmaf(z, kv, a1.z);
        z = fmaf(z, kv, a1.y);
        z = fmaf(z, kv, a1.x);
        z = fmaf(z, kv, a0.w);
        z = fmaf(z, kv, a0.z);
        z = fmaf(z, kv, a0.y);
        z = fmaf(z, kv, a0.x);
        float W = rcpf(z);
        float4 h0 = *(const float4*)(&s_H[sn][0]);
        float4 h1 = *(const float4*)(&s_H[sn][4]);
        float  h8 = s_H[sn][8];
        T[0] = fmaf(h0.x, W, T[0]);
        T[1] = fmaf(h0.y, W, T[1]);
        T[2] = fmaf(h0.z, W, T[2]);
        T[3] = fmaf(h0.w, W, T[3]);
        T[4] = fmaf(h1.x, W, T[4]);
        T[5] = fmaf(h1.y, W, T[5]);
        T[6] = fmaf(h1.z, W, T[6]);
        T[7] = fmaf(h1.w, W, T[7]);
        T[8] = fmaf(h8,   W, T[8]);
    }
    {
        float kp = vv;
        #pragma unroll
        for (int n = 0; n < 9; n++) { T[n] *= kp; kp *= kv; }
    }

    // warp-reduce 16 (padded) values: halving over bits 4..1 + final bit-0 stage
    {
        float rv[16];
        #pragma unroll
        for (int i = 0; i < 9; i++) rv[i] = T[i];
        #pragma unroll
        for (int i = 9; i < 16; i++) rv[i] = 0.f;
        #pragma unroll
        for (int r = 0; r < 8; r++) {
            float lo = rv[r], hi = rv[r + 8];
            float keep = (lane & 16) ? hi : lo, send = (lane & 16) ? lo : hi;
            rv[r] = keep + __shfl_xor_sync(0xffffffffu, send, 16);
        }
        #pragma unroll
        for (int r = 0; r < 4; r++) {
            float lo = rv[r], hi = rv[r + 4];
            float keep = (lane & 8) ? hi : lo, send = (lane & 8) ? lo : hi;
            rv[r] = keep + __shfl_xor_sync(0xffffffffu, send, 8);
        }
        #pragma unroll
        for (int r = 0; r < 2; r++) {
            float lo = rv[r], hi = rv[r + 2];
            float keep = (lane & 4) ? hi : lo, send = (lane & 4) ? lo : hi;
            rv[r] = keep + __shfl_xor_sync(0xffffffffu, send, 4);
        }
        {
            float lo = rv[0], hi = rv[1];
            float keep = (lane & 2) ? hi : lo, send = (lane & 2) ? lo : hi;
            rv[0] = keep + __shfl_xor_sync(0xffffffffu, send, 2);
        }
        rv[0] += __shfl_xor_sync(0xffffffffu, rv[0], 1);
        int j = lane >> 1;
        if (((lane & 1) == 0) && j < 9) s_red[warp][j] = rv[0];
    }
    __syncthreads();
    if (t < 18) {
        int hh = t / 9, n = t - hh * 9;
        s_C[hh][n] = (s_red[4 * hh][n] + s_red[4 * hh + 1][n])
                   + (s_red[4 * hh + 2][n] + s_red[4 * hh + 3][n]);
    }
    __syncthreads();

    // out[rm] = sum_n qv^n * C[n] (Horner), + residual
    float r = s_C[h][8];
    #pragma unroll
    for (int n = 7; n >= 0; n--) r = fmaf(r, qv, s_C[h][n]);
    const float x = qv + r;

    // ── LayerNorm across the 2048-row via cluster DSMEM ──
    float s1 = x, s2 = x * x;
    #pragma unroll
    for (int o = 16; o; o >>= 1) {
        s1 += __shfl_xor_sync(0xffffffffu, s1, o);
        s2 += __shfl_xor_sync(0xffffffffu, s2, o);
    }
    if (lane == 0) { s_l1[warp] = s1; s_l2[warp] = s2; }
    __syncthreads();
    if (t == 0) {
        float ts = 0.f, ts2 = 0.f;
        #pragma unroll
        for (int w = 0; w < 8; w++) { ts += s_l1[w]; ts2 += s_l2[w]; }
        s_lnp[0] = ts;
        s_lnp[1] = ts2;
    }
    // no __syncthreads: t0's s_lnp store precedes t0's arrive; peers read after wait.
    CLUSTER_SYNC();                       // partials visible cluster-wide
    if (t < 8) {                          // parallel remote gather
        s_l1[t] = dsmem_ld(smem_u32(&s_lnp[0]), (uint32_t)t);
        s_l2[t] = dsmem_ld(smem_u32(&s_lnp[1]), (uint32_t)t);
    }
    __syncthreads();

    // all threads compute mu/rstd from the 8 partials (broadcast LDS, fixed order)
    float S = 0.f, S2 = 0.f;
    #pragma unroll
    for (int j = 0; j < 8; j++) { S += s_l1[j]; S2 += s_l2[j]; }
    const float mu   = S * (1.f / 2048.f);
    const float var  = S2 * (1.f / 2048.f) - mu * mu;
    const float rstd = rsqrtf(var + 1e-5f);

    out[base + t] = (x - mu) * rstd * wl + bl;

    CLUSTER_SYNC();                       // keep smem alive for peers' DSMEM reads
}

extern "C" void kernel_launch(void* const* d_in, const int* in_sizes, int n_in,
                              void* d_out, int out_size) {
    const float* query = (const float*)d_in[0];
    const float* key   = (const float*)d_in[1];
    const float* value = (const float*)d_in[2];
    const float* wq    = (const float*)d_in[3];
    const float* wk    = (const float*)d_in[4];
    const float* wv    = (const float*)d_in[5];
    const float* wf    = (const float*)d_in[6];
    const float* lnw   = (const float*)d_in[7];
    const float* lnb   = (const float*)d_in[8];
    float* out = (float*)d_out;

    fused_all<<<32, 256>>>(query, key, value, wq, wk, wv, wf, lnw, lnb, out);
}